// round 14
// baseline (speedup 1.0000x reference)
#include <cuda_runtime.h>
#include <cuda_fp16.h>
#include <math.h>
#include <stdint.h>

// Problem shapes (fixed by the reference)
#define BATCH 16
#define KQ    512
#define NK    2048
#define DIM   1024

// ---------------- scratch (no cudaMalloc allowed) ----------------
__device__ float  g_qW_part[8 * KQ * DIM];              // 16 MB split-K partials
__device__ __half g_qW_h[KQ * DIM];                     // 1 MB
__device__ __half g_query_h[KQ * DIM];                  // 1 MB
__device__ __half g_WT_h[DIM * DIM];                    // 2 MB  W^T [j][d]
__device__ __half g_key_h[(size_t)BATCH * NK * DIM];    // 64 MB key (half, native layout)
__device__ float  g_att_scratch[(size_t)BATCH * KQ * NK]; // 64 MB (if att not in d_out)
__device__ __half g_att_h[(size_t)BATCH * KQ * NK];     // 64 MB half att
__device__ int    g_mask_kind;                          // 0=int32, 1=uint8, 2=float32

// ---------------- helpers ----------------
__device__ __forceinline__ void cp16(uint32_t s, const void* g) {
    asm volatile("cp.async.cg.shared.global [%0], [%1], 16;" :: "r"(s), "l"(g));
}
__device__ __forceinline__ void cp_commit() {
    asm volatile("cp.async.commit_group;" ::: "memory");
}
__device__ __forceinline__ void cp_wait1() {
    asm volatile("cp.async.wait_group 1;" ::: "memory");
}
__device__ __forceinline__ void mma_f16(float* c, uint32_t a0, uint32_t a1,
                                        uint32_t a2, uint32_t a3,
                                        uint32_t b0, uint32_t b1) {
    asm volatile(
        "mma.sync.aligned.m16n8k16.row.col.f32.f16.f16.f32 "
        "{%0,%1,%2,%3}, {%4,%5,%6,%7}, {%8,%9}, {%0,%1,%2,%3};"
        : "+f"(c[0]), "+f"(c[1]), "+f"(c[2]), "+f"(c[3])
        : "r"(a0), "r"(a1), "r"(a2), "r"(a3), "r"(b0), "r"(b1));
}
__device__ __forceinline__ void ldsm4(uint32_t* r, uint32_t a) {
    asm volatile("ldmatrix.sync.aligned.m8n8.x4.shared.b16 {%0,%1,%2,%3}, [%4];"
        : "=r"(r[0]), "=r"(r[1]), "=r"(r[2]), "=r"(r[3]) : "r"(a));
}
__device__ __forceinline__ void ldsm4t(uint32_t* r, uint32_t a) {
    asm volatile("ldmatrix.sync.aligned.m8n8.x4.trans.shared.b16 {%0,%1,%2,%3}, [%4];"
        : "=r"(r[0]), "=r"(r[1]), "=r"(r[2]), "=r"(r[3]) : "r"(a));
}

#define HST 40    // A / NT-B tile row stride (halfs): 32 data + 8 pad
#define SBN 136   // NN-B tile row stride (halfs): 128 data + 8 pad

#define STGA_B (128 * HST * 2)      // 10240 bytes per A (or NT-B) stage
#define STGB_B (32 * SBN * 2)       // 8704 bytes per NN-B stage
#define SMEM_NT (3 * 2 * STGA_B)    // 61440
#define SMEM_NN (3 * (STGA_B + STGB_B))  // 56832

// =====================================================================
// fp16 mma GEMM, NT: C[M,N] = A[M,Kd] * B[N,Kd]^T  (both K-contig half)
// Block 128x128, 8 warps (2x4), warp tile 64x32, K-chunk 32 halfs,
// 3-stage cp.async pipeline, ldmatrix fragment loads.
// =====================================================================
__global__ void __launch_bounds__(256) gemm_nt_h(
    const __half* __restrict__ A, const __half* __restrict__ B, float* __restrict__ C,
    int Kd, int lda, int ldb, int ldc, long sA, long sB, long sC)
{
    extern __shared__ char smem[];

    const int tid  = threadIdx.x;
    const int wid  = tid >> 5;
    const int lane = tid & 31;
    const int wm   = wid & 1;        // 64-row half
    const int wn   = wid >> 1;       // 0..3 -> 32-col quarter
    const int grp  = lane >> 2;
    const int tig  = lane & 3;

    A += (long)blockIdx.z * sA + (long)blockIdx.y * 128 * lda;
    B += (long)blockIdx.z * sB + (long)blockIdx.x * 128 * ldb;
    C += (long)blockIdx.z * sC + (long)blockIdx.y * 128 * ldc + (long)blockIdx.x * 128;

    const int crow = tid >> 2;          // cp rows 0..63 (+64)
    const int cseg = (tid & 3) * 8;

    const uint32_t sa0 = (uint32_t)__cvta_generic_to_shared(smem);
    const uint32_t sb0 = sa0 + 3 * STGA_B;

    const uint32_t offA = (uint32_t)(((wm * 64 + (lane & 15)) * HST + 8 * (lane >> 4)) * 2);
    const uint32_t offB = (uint32_t)(((wn * 32 + (lane & 7) + 8 * (lane >> 4)) * HST
                                      + 8 * ((lane >> 3) & 1)) * 2);

    float acc[4][4][4];
    #pragma unroll
    for (int i = 0; i < 4; i++)
        #pragma unroll
        for (int j = 0; j < 4; j++)
            #pragma unroll
            for (int t = 0; t < 4; t++) acc[i][j][t] = 0.f;

    const int NCH = Kd >> 5;
    const uint32_t cpa = (uint32_t)(crow * HST + cseg) * 2;

    // prologue: chunks 0,1 -> stages 0,1
    #pragma unroll
    for (int p = 0; p < 2; p++) {
        if (p < NCH) {
            const __half* Ap = A + (long)p * 32;
            const __half* Bp = B + (long)p * 32;
            #pragma unroll
            for (int i = 0; i < 2; i++) {
                int row = crow + 64 * i;
                uint32_t d = cpa + (uint32_t)(i * 64 * HST * 2);
                cp16(sa0 + p * STGA_B + d, Ap + (long)row * lda + cseg);
                cp16(sb0 + p * STGA_B + d, Bp + (long)row * ldb + cseg);
            }
        }
        cp_commit();
    }

    for (int kc = 0; kc < NCH; kc++) {
        cp_wait1();
        __syncthreads();

        if (kc + 2 < NCH) {
            const uint32_t st = (uint32_t)((kc + 2) % 3);
            const __half* An = A + (long)(kc + 2) * 32;
            const __half* Bn = B + (long)(kc + 2) * 32;
            #pragma unroll
            for (int i = 0; i < 2; i++) {
                int row = crow + 64 * i;
                uint32_t d = cpa + (uint32_t)(i * 64 * HST * 2);
                cp16(sa0 + st * STGA_B + d, An + (long)row * lda + cseg);
                cp16(sb0 + st * STGA_B + d, Bn + (long)row * ldb + cseg);
            }
        }
        cp_commit();

        const uint32_t so = (uint32_t)(kc % 3) * STGA_B;
        #pragma unroll
        for (int g = 0; g < 2; g++) {
            uint32_t afr[4][4], bfr[2][4];
            #pragma unroll
            for (int mt = 0; mt < 4; mt++)
                ldsm4(afr[mt], sa0 + so + offA + (uint32_t)(mt * 16 * HST * 2 + g * 32));
            #pragma unroll
            for (int np = 0; np < 2; np++)
                ldsm4(bfr[np], sb0 + so + offB + (uint32_t)(np * 16 * HST * 2 + g * 32));
            #pragma unroll
            for (int mt = 0; mt < 4; mt++)
                #pragma unroll
                for (int np = 0; np < 2; np++) {
                    mma_f16(acc[mt][2 * np],     afr[mt][0], afr[mt][1], afr[mt][2], afr[mt][3],
                            bfr[np][0], bfr[np][1]);
                    mma_f16(acc[mt][2 * np + 1], afr[mt][0], afr[mt][1], afr[mt][2], afr[mt][3],
                            bfr[np][2], bfr[np][3]);
                }
        }
    }

    #pragma unroll
    for (int mt = 0; mt < 4; mt++) {
        int r0 = wm * 64 + mt * 16 + grp;
        #pragma unroll
        for (int nt = 0; nt < 4; nt++) {
            int c0 = wn * 32 + nt * 8 + 2 * tig;
            *(float2*)(C + (long)r0 * ldc + c0)       = make_float2(acc[mt][nt][0], acc[mt][nt][1]);
            *(float2*)(C + (long)(r0 + 8) * ldc + c0) = make_float2(acc[mt][nt][2], acc[mt][nt][3]);
        }
    }
}

// =====================================================================
// fp16 mma GEMM, NN: C[M,N] = A[M,Kd] * B[Kd,N]  (B row-major half)
// 3-stage pipeline; B fragments via ldmatrix.trans.
// =====================================================================
__global__ void __launch_bounds__(256) gemm_nn_h(
    const __half* __restrict__ A, const __half* __restrict__ B, float* __restrict__ C,
    int Kd, int lda, int ldb, int ldc, long sA, long sB, long sC)
{
    extern __shared__ char smem[];

    const int tid  = threadIdx.x;
    const int wid  = tid >> 5;
    const int lane = tid & 31;
    const int wm   = wid & 1;
    const int wn   = wid >> 1;
    const int grp  = lane >> 2;
    const int tig  = lane & 3;

    A += (long)blockIdx.z * sA + (long)blockIdx.y * 128 * lda;
    B += (long)blockIdx.z * sB + (long)blockIdx.x * 128;
    C += (long)blockIdx.z * sC + (long)blockIdx.y * 128 * ldc + (long)blockIdx.x * 128;

    const int crow = tid >> 2;          // A cp rows 0..63 (+64)
    const int cseg = (tid & 3) * 8;
    const int brow = tid >> 4;          // B cp rows 0..15 (+16)
    const int bseg = (tid & 15) * 8;

    const uint32_t sa0 = (uint32_t)__cvta_generic_to_shared(smem);
    const uint32_t sb0 = sa0 + 3 * STGA_B;

    const uint32_t offA = (uint32_t)(((wm * 64 + (lane & 15)) * HST + 8 * (lane >> 4)) * 2);
    const uint32_t offB = (uint32_t)((((lane & 7) + 8 * ((lane >> 3) & 1)) * SBN
                                      + wn * 32 + 8 * (lane >> 4)) * 2);

    float acc[4][4][4];
    #pragma unroll
    for (int i = 0; i < 4; i++)
        #pragma unroll
        for (int j = 0; j < 4; j++)
            #pragma unroll
            for (int t = 0; t < 4; t++) acc[i][j][t] = 0.f;

    const int NCH = Kd >> 5;
    const uint32_t cpa = (uint32_t)(crow * HST + cseg) * 2;
    const uint32_t cpb = (uint32_t)(brow * SBN + bseg) * 2;

    #pragma unroll
    for (int p = 0; p < 2; p++) {
        if (p < NCH) {
            const __half* Ap = A + (long)p * 32;
            const __half* Bp = B + (long)p * 32 * ldb;
            #pragma unroll
            for (int i = 0; i < 2; i++) {
                int arow = crow + 64 * i;
                cp16(sa0 + p * STGA_B + cpa + (uint32_t)(i * 64 * HST * 2),
                     Ap + (long)arow * lda + cseg);
                int kr = brow + 16 * i;
                cp16(sb0 + p * STGB_B + cpb + (uint32_t)(i * 16 * SBN * 2),
                     Bp + (long)kr * ldb + bseg);
            }
        }
        cp_commit();
    }

    for (int kc = 0; kc < NCH; kc++) {
        cp_wait1();
        __syncthreads();

        if (kc + 2 < NCH) {
            const uint32_t st = (uint32_t)((kc + 2) % 3);
            const __half* An = A + (long)(kc + 2) * 32;
            const __half* Bn = B + (long)(kc + 2) * 32 * ldb;
            #pragma unroll
            for (int i = 0; i < 2; i++) {
                int arow = crow + 64 * i;
                cp16(sa0 + st * STGA_B + cpa + (uint32_t)(i * 64 * HST * 2),
                     An + (long)arow * lda + cseg);
                int kr = brow + 16 * i;
                cp16(sb0 + st * STGB_B + cpb + (uint32_t)(i * 16 * SBN * 2),
                     Bn + (long)kr * ldb + bseg);
            }
        }
        cp_commit();

        const uint32_t soA = (uint32_t)(kc % 3) * STGA_B;
        const uint32_t soB = (uint32_t)(kc % 3) * STGB_B;
        #pragma unroll
        for (int g = 0; g < 2; g++) {
            uint32_t afr[4][4], bfr[2][4];
            #pragma unroll
            for (int mt = 0; mt < 4; mt++)
                ldsm4(afr[mt], sa0 + soA + offA + (uint32_t)(mt * 16 * HST * 2 + g * 32));
            #pragma unroll
            for (int np = 0; np < 2; np++)
                ldsm4t(bfr[np], sb0 + soB + offB + (uint32_t)(np * 32 + g * 16 * SBN * 2));
            #pragma unroll
            for (int mt = 0; mt < 4; mt++)
                #pragma unroll
                for (int np = 0; np < 2; np++) {
                    mma_f16(acc[mt][2 * np],     afr[mt][0], afr[mt][1], afr[mt][2], afr[mt][3],
                            bfr[np][0], bfr[np][1]);
                    mma_f16(acc[mt][2 * np + 1], afr[mt][0], afr[mt][1], afr[mt][2], afr[mt][3],
                            bfr[np][2], bfr[np][3]);
                }
        }
    }

    #pragma unroll
    for (int mt = 0; mt < 4; mt++) {
        int r0 = wm * 64 + mt * 16 + grp;
        #pragma unroll
        for (int nt = 0; nt < 4; nt++) {
            int c0 = wn * 32 + nt * 8 + 2 * tig;
            *(float2*)(C + (long)r0 * ldc + c0)       = make_float2(acc[mt][nt][0], acc[mt][nt][1]);
            *(float2*)(C + (long)(r0 + 8) * ldc + c0) = make_float2(acc[mt][nt][2], acc[mt][nt][3]);
        }
    }
}

// ---------------- conversion kernels ----------------
__global__ void __launch_bounds__(256) f32_to_f16_vec(
    const float* __restrict__ src, __half* __restrict__ dst)
{
    long i = (long)blockIdx.x * 256 + threadIdx.x;
    float4 v = ((const float4*)src)[i];
    ((__half2*)dst)[2 * i]     = __floats2half2_rn(v.x, v.y);
    ((__half2*)dst)[2 * i + 1] = __floats2half2_rn(v.z, v.w);
}

// dst[C][R] (half) = src[R][C]^T (f32)  -- used for W^T only
__global__ void __launch_bounds__(256) transpose_f16(
    const float* __restrict__ src, __half* __restrict__ dst, int R, int C)
{
    __shared__ float t[32][33];
    int c0 = blockIdx.x * 32, r0 = blockIdx.y * 32;
    int x = threadIdx.x, y = threadIdx.y;
    #pragma unroll
    for (int i = 0; i < 32; i += 8)
        t[y + i][x] = src[(long)(r0 + y + i) * C + c0 + x];
    __syncthreads();
    #pragma unroll
    for (int i = 0; i < 32; i += 8)
        dst[(long)(c0 + y + i) * R + r0 + x] = __float2half(t[x][y + i]);
}

// ---------------- split-K reduction for qW (writes half) ----------------
__global__ void __launch_bounds__(256) reduce_qw(
    const float* __restrict__ part, __half* __restrict__ qW_h)
{
    int i = (blockIdx.x * 256 + threadIdx.x) * 4;
    float4 s = make_float4(0.f, 0.f, 0.f, 0.f);
    #pragma unroll
    for (int z = 0; z < 8; z++) {
        float4 v = *(const float4*)(part + (long)z * (KQ * DIM) + i);
        s.x += v.x; s.y += v.y; s.z += v.z; s.w += v.w;
    }
    const float a = 1.0f / 32.0f;
    ((__half2*)qW_h)[i / 2]     = __floats2half2_rn(s.x * a, s.y * a);
    ((__half2*)qW_h)[i / 2 + 1] = __floats2half2_rn(s.z * a, s.w * a);
}

// ---------------- mask dtype detection ----------------
__global__ void detect_mask_kind(const unsigned char* __restrict__ m)
{
    if (threadIdx.x != 0 || blockIdx.x != 0) return;
    int cnt[4] = {0, 0, 0, 0};
    for (int i = 0; i < 4096; i++)
        if (m[i] != 0) cnt[i & 3]++;
    int kind;
    if (cnt[1] > 0)                    kind = 1;  // uint8 bool
    else if (cnt[2] > 0 || cnt[3] > 0) kind = 2;  // float32
    else                               kind = 0;  // int32 bool
    g_mask_kind = kind;
}

// ---------------- fused mask + softmax (fp32 att + half att) ----------------
__global__ void __launch_bounds__(256) mask_softmax(
    float* __restrict__ att, __half* __restrict__ att_h, const void* __restrict__ mask_raw)
{
    long row = blockIdx.x;
    float* p = att + row * (long)NK;
    __half* ph = att_h + row * (long)NK;
    int tid = threadIdx.x;
    int kind = g_mask_kind;

    const unsigned char* m8  = (const unsigned char*)mask_raw + row * (long)NK;
    const int*           m32 = (const int*)mask_raw           + row * (long)NK;
    const float*         mf  = (const float*)mask_raw         + row * (long)NK;

    float v[8];
    float lmax = -INFINITY;
    #pragma unroll
    for (int i = 0; i < 8; i++) {
        int idx = tid + i * 256;
        bool keep;
        if (kind == 0)      keep = (m32[idx] != 0);
        else if (kind == 1) keep = (m8[idx] != 0);
        else                keep = (mf[idx] != 0.0f);
        float s = keep ? p[idx] : -INFINITY;
        v[i] = s;
        lmax = fmaxf(lmax, s);
    }

    __shared__ float red[8];
    #pragma unroll
    for (int o = 16; o > 0; o >>= 1)
        lmax = fmaxf(lmax, __shfl_xor_sync(0xffffffffu, lmax, o));
    if ((tid & 31) == 0) red[tid >> 5] = lmax;
    __syncthreads();
    float rmax = fmaxf(fmaxf(fmaxf(red[0], red[1]), fmaxf(red[2], red[3])),
                       fmaxf(fmaxf(red[4], red[5]), fmaxf(red[6], red[7])));
    __syncthreads();

    float lsum = 0.f;
    #pragma unroll
    for (int i = 0; i < 8; i++) {
        float e = (v[i] == -INFINITY) ? 0.f : __expf(v[i] - rmax);
        v[i] = e;
        lsum += e;
    }
    #pragma unroll
    for (int o = 16; o > 0; o >>= 1)
        lsum += __shfl_xor_sync(0xffffffffu, lsum, o);
    if ((tid & 31) == 0) red[tid >> 5] = lsum;
    __syncthreads();
    float rsum = red[0] + red[1] + red[2] + red[3] + red[4] + red[5] + red[6] + red[7];
    float inv = (rsum > 0.f) ? (1.f / rsum) : 0.f;

    #pragma unroll
    for (int i = 0; i < 8; i++) {
        float r = v[i] * inv;
        int idx = tid + i * 256;
        p[idx] = r;
        ph[idx] = __float2half(r);
    }
}

// ---------------- launcher ----------------
extern "C" void kernel_launch(void* const* d_in, const int* in_sizes, int n_in,
                              void* d_out, int out_size)
{
    const float* query = (const float*)d_in[0];   // [KQ, DIM]
    const float* key   = (const float*)d_in[1];   // [BATCH, NK, DIM]
    const float* W     = (const float*)d_in[2];   // [DIM, DIM]
    const void*  mask  = d_in[3];                 // [BATCH, KQ, NK] bool

    float* out_ptr = (float*)d_out;
    const long outBKD = (long)BATCH * KQ * DIM;

    float *qW_part, *att_scratch;
    __half *qW_h, *query_h, *WT_h, *key_h, *att_h;
    cudaGetSymbolAddress((void**)&qW_part, g_qW_part);
    cudaGetSymbolAddress((void**)&qW_h, g_qW_h);
    cudaGetSymbolAddress((void**)&query_h, g_query_h);
    cudaGetSymbolAddress((void**)&WT_h, g_WT_h);
    cudaGetSymbolAddress((void**)&key_h, g_key_h);
    cudaGetSymbolAddress((void**)&att_h, g_att_h);
    cudaGetSymbolAddress((void**)&att_scratch, g_att_scratch);

    float* att_ptr = ((long)out_size > outBKD) ? (out_ptr + outBKD) : att_scratch;

    cudaFuncSetAttribute(gemm_nt_h, cudaFuncAttributeMaxDynamicSharedMemorySize, SMEM_NT);
    cudaFuncSetAttribute(gemm_nn_h, cudaFuncAttributeMaxDynamicSharedMemorySize, SMEM_NN);

    // 0) mask dtype detection
    detect_mask_kind<<<1, 1>>>((const unsigned char*)mask);

    // 1) conversions: query -> half, W -> W^T half, key -> half (native layout)
    f32_to_f16_vec<<<(KQ * DIM / 4) / 256, 256>>>(query, query_h);
    transpose_f16<<<dim3(DIM / 32, DIM / 32), dim3(32, 8)>>>(W, WT_h, DIM, DIM);
    f32_to_f16_vec<<<(int)(((long)BATCH * NK * DIM / 4) / 256), 256>>>(key, key_h);

    // 2) qW partials via split-K=8 (NT: A=query_h, B=WT_h), then reduce (/32) -> half
    gemm_nt_h<<<dim3(DIM / 128, KQ / 128, 8), 256, SMEM_NT>>>(
        query_h, WT_h, qW_part, 128, DIM, DIM, DIM,
        128L, 128L, (long)KQ * DIM);
    reduce_qw<<<KQ * DIM / (256 * 4), 256>>>(qW_part, qW_h);

    // 3) scores[b] = qW_h @ key_h[b]^T   (NT)
    gemm_nt_h<<<dim3(NK / 128, KQ / 128, BATCH), 256, SMEM_NT>>>(
        qW_h, key_h, att_ptr, DIM, DIM, DIM, NK,
        0L, (long)NK * DIM, (long)KQ * NK);

    // 4) mask + softmax in place (fp32 out) + half copy
    mask_softmax<<<BATCH * KQ, 256>>>(att_ptr, att_h, mask);

    // 5) out[b] = att_h[b] @ key_h[b]    (NN, B in native [n][d] layout)
    gemm_nn_h<<<dim3(DIM / 128, KQ / 128, BATCH), 256, SMEM_NN>>>(
        att_h, key_h, out_ptr, NK, NK, DIM, DIM,
        (long)KQ * NK, (long)NK * DIM, (long)KQ * DIM);
}

// round 15
// speedup vs baseline: 1.5753x; 1.5753x over previous
#include <cuda_runtime.h>
#include <cuda_fp16.h>
#include <math.h>
#include <stdint.h>

// Problem shapes (fixed by the reference)
#define BATCH 16
#define KQ    512
#define NK    2048
#define DIM   1024

// ---------------- scratch (no cudaMalloc allowed) ----------------
__device__ float  g_qW_part[8 * KQ * DIM];              // 16 MB split-K partials
__device__ __half g_qW_h[KQ * DIM];                     // 1 MB
__device__ __half g_query_h[KQ * DIM];                  // 1 MB
__device__ float  g_WT_f[DIM * DIM];                    // 4 MB  W^T [j][d] (f32)
__device__ float  g_att_scratch[(size_t)BATCH * KQ * NK]; // 64 MB (if att not in d_out)
__device__ __half g_att_h[(size_t)BATCH * KQ * NK];     // 64 MB half att
__device__ int    g_mask_kind;                          // 0=int32, 1=uint8, 2=float32

// ---------------- helpers ----------------
__device__ __forceinline__ void cp16(uint32_t s, const void* g) {
    asm volatile("cp.async.cg.shared.global [%0], [%1], 16;" :: "r"(s), "l"(g));
}
__device__ __forceinline__ void cp_commit() {
    asm volatile("cp.async.commit_group;" ::: "memory");
}
__device__ __forceinline__ void cp_wait0() {
    asm volatile("cp.async.wait_group 0;" ::: "memory");
}
__device__ __forceinline__ void mma_f16(float* c, uint32_t a0, uint32_t a1,
                                        uint32_t a2, uint32_t a3,
                                        uint32_t b0, uint32_t b1) {
    asm volatile(
        "mma.sync.aligned.m16n8k16.row.col.f32.f16.f16.f32 "
        "{%0,%1,%2,%3}, {%4,%5,%6,%7}, {%8,%9}, {%0,%1,%2,%3};"
        : "+f"(c[0]), "+f"(c[1]), "+f"(c[2]), "+f"(c[3])
        : "r"(a0), "r"(a1), "r"(a2), "r"(a3), "r"(b0), "r"(b1));
}
__device__ __forceinline__ void ldsm4(uint32_t* r, uint32_t a) {
    asm volatile("ldmatrix.sync.aligned.m8n8.x4.shared.b16 {%0,%1,%2,%3}, [%4];"
        : "=r"(r[0]), "=r"(r[1]), "=r"(r[2]), "=r"(r[3]) : "r"(a));
}
__device__ __forceinline__ void ldsm4t(uint32_t* r, uint32_t a) {
    asm volatile("ldmatrix.sync.aligned.m8n8.x4.trans.shared.b16 {%0,%1,%2,%3}, [%4];"
        : "=r"(r[0]), "=r"(r[1]), "=r"(r[2]), "=r"(r[3]) : "r"(a));
}
__device__ __forceinline__ uint32_t h2u(__half2 h) { return *(uint32_t*)&h; }

#define HST 40    // A / NT-B tile row stride (halfs): 32 data + 8 pad
#define SBN 136   // NN-B tile row stride (halfs): 128 data + 8 pad

// =====================================================================
// fp16 mma GEMM, NT: C[M,N] = A[M,Kd](half) * B[N,Kd]^T(FLOAT, converted in-kernel)
// Block 128x128, 8 warps (2x4), warp tile 64x32, K-chunk 32,
// A: 2-stage cp.async; B: LDG.f32 prefetch + CVT + STS; ldmatrix fragments.
// =====================================================================
__global__ void __launch_bounds__(256) gemm_nt_h(
    const __half* __restrict__ A, const float* __restrict__ Bf, float* __restrict__ C,
    int Kd, int lda, int ldb, int ldc, long sA, long sB, long sC)
{
    __shared__ __half As[2][128 * HST];
    __shared__ __half Bs[2][128 * HST];

    const int tid  = threadIdx.x;
    const int wid  = tid >> 5;
    const int lane = tid & 31;
    const int wm   = wid & 1;        // 64-row half
    const int wn   = wid >> 1;       // 0..3 -> 32-col quarter
    const int grp  = lane >> 2;
    const int tig  = lane & 3;

    A  += (long)blockIdx.z * sA + (long)blockIdx.y * 128 * lda;
    Bf += (long)blockIdx.z * sB + (long)blockIdx.x * 128 * ldb;
    C  += (long)blockIdx.z * sC + (long)blockIdx.y * 128 * ldc + (long)blockIdx.x * 128;

    const int crow = tid >> 2;          // 0..63 (+64)
    const int cseg = (tid & 3) * 8;     // 8-elem segment

    const uint32_t sa0 = (uint32_t)__cvta_generic_to_shared(&As[0][0]);
    const uint32_t stgA = (uint32_t)(128 * HST * 2);

    const uint32_t offA = (uint32_t)(((wm * 64 + (lane & 15)) * HST + 8 * (lane >> 4)) * 2);
    const uint32_t offB = (uint32_t)(((wn * 32 + (lane & 7) + 8 * (lane >> 4)) * HST
                                      + 8 * ((lane >> 3) & 1)) * 2);
    const uint32_t sb0 = (uint32_t)__cvta_generic_to_shared(&Bs[0][0]);

    float acc[4][4][4];
    #pragma unroll
    for (int i = 0; i < 4; i++)
        #pragma unroll
        for (int j = 0; j < 4; j++)
            #pragma unroll
            for (int t = 0; t < 4; t++) acc[i][j][t] = 0.f;

    const int NCH = Kd >> 5;
    const uint32_t cpa = (uint32_t)(crow * HST + cseg) * 2;

    float4 pb[2][2];

    // prologue: chunk 0
    #pragma unroll
    for (int i = 0; i < 2; i++) {
        int row = crow + 64 * i;
        const float* bp = Bf + (long)row * ldb + cseg;
        pb[i][0] = *(const float4*)bp;
        pb[i][1] = *(const float4*)(bp + 4);
        cp16(sa0 + cpa + (uint32_t)(i * 64 * HST * 2), A + (long)row * lda + cseg);
    }
    cp_commit();
    #pragma unroll
    for (int i = 0; i < 2; i++) {
        int row = crow + 64 * i;
        uint4 u;
        u.x = h2u(__floats2half2_rn(pb[i][0].x, pb[i][0].y));
        u.y = h2u(__floats2half2_rn(pb[i][0].z, pb[i][0].w));
        u.z = h2u(__floats2half2_rn(pb[i][1].x, pb[i][1].y));
        u.w = h2u(__floats2half2_rn(pb[i][1].z, pb[i][1].w));
        *(uint4*)&Bs[0][row * HST + cseg] = u;
    }

    for (int kc = 0; kc < NCH; kc++) {
        // prefetch B chunk kc+1 (f32, lands during compute below)
        if (kc + 1 < NCH) {
            const float* Bn = Bf + (long)(kc + 1) * 32;
            #pragma unroll
            for (int i = 0; i < 2; i++) {
                const float* bp = Bn + (long)(crow + 64 * i) * ldb + cseg;
                pb[i][0] = *(const float4*)bp;
                pb[i][1] = *(const float4*)(bp + 4);
            }
        }

        cp_wait0();
        __syncthreads();   // A(kc) + B(kc) visible; stage sn free

        const int sn = (kc + 1) & 1;
        if (kc + 1 < NCH) {
            const __half* An = A + (long)(kc + 1) * 32;
            #pragma unroll
            for (int i = 0; i < 2; i++)
                cp16(sa0 + (uint32_t)sn * stgA + cpa + (uint32_t)(i * 64 * HST * 2),
                     An + (long)(crow + 64 * i) * lda + cseg);
            cp_commit();
        }

        const uint32_t so = (uint32_t)(kc & 1) * stgA;
        #pragma unroll
        for (int g = 0; g < 2; g++) {
            uint32_t afr[4][4], bfr[2][4];
            #pragma unroll
            for (int mt = 0; mt < 4; mt++)
                ldsm4(afr[mt], sa0 + so + offA + (uint32_t)(mt * 16 * HST * 2 + g * 32));
            #pragma unroll
            for (int np = 0; np < 2; np++)
                ldsm4(bfr[np], sb0 + so + offB + (uint32_t)(np * 16 * HST * 2 + g * 32));
            #pragma unroll
            for (int mt = 0; mt < 4; mt++)
                #pragma unroll
                for (int np = 0; np < 2; np++) {
                    mma_f16(acc[mt][2 * np],     afr[mt][0], afr[mt][1], afr[mt][2], afr[mt][3],
                            bfr[np][0], bfr[np][1]);
                    mma_f16(acc[mt][2 * np + 1], afr[mt][0], afr[mt][1], afr[mt][2], afr[mt][3],
                            bfr[np][2], bfr[np][3]);
                }
        }

        // store B chunk kc+1 into stage sn (barrier at top of next iter publishes it)
        if (kc + 1 < NCH) {
            #pragma unroll
            for (int i = 0; i < 2; i++) {
                int row = crow + 64 * i;
                uint4 u;
                u.x = h2u(__floats2half2_rn(pb[i][0].x, pb[i][0].y));
                u.y = h2u(__floats2half2_rn(pb[i][0].z, pb[i][0].w));
                u.z = h2u(__floats2half2_rn(pb[i][1].x, pb[i][1].y));
                u.w = h2u(__floats2half2_rn(pb[i][1].z, pb[i][1].w));
                *(uint4*)&Bs[sn][row * HST + cseg] = u;
            }
        }
    }

    #pragma unroll
    for (int mt = 0; mt < 4; mt++) {
        int r0 = wm * 64 + mt * 16 + grp;
        #pragma unroll
        for (int nt = 0; nt < 4; nt++) {
            int c0 = wn * 32 + nt * 8 + 2 * tig;
            *(float2*)(C + (long)r0 * ldc + c0)       = make_float2(acc[mt][nt][0], acc[mt][nt][1]);
            *(float2*)(C + (long)(r0 + 8) * ldc + c0) = make_float2(acc[mt][nt][2], acc[mt][nt][3]);
        }
    }
}

// =====================================================================
// fp16 mma GEMM, NN: C[M,N] = A[M,Kd](half) * B[Kd,N](FLOAT, converted in-kernel)
// B tile [32 k][128 n]; B fragments via ldmatrix.trans.
// =====================================================================
__global__ void __launch_bounds__(256) gemm_nn_h(
    const __half* __restrict__ A, const float* __restrict__ Bf, float* __restrict__ C,
    int Kd, int lda, int ldb, int ldc, long sA, long sB, long sC)
{
    __shared__ __half As[2][128 * HST];
    __shared__ __half Bs[2][32 * SBN];

    const int tid  = threadIdx.x;
    const int wid  = tid >> 5;
    const int lane = tid & 31;
    const int wm   = wid & 1;
    const int wn   = wid >> 1;
    const int grp  = lane >> 2;
    const int tig  = lane & 3;

    A  += (long)blockIdx.z * sA + (long)blockIdx.y * 128 * lda;
    Bf += (long)blockIdx.z * sB + (long)blockIdx.x * 128;
    C  += (long)blockIdx.z * sC + (long)blockIdx.y * 128 * ldc + (long)blockIdx.x * 128;

    const int crow = tid >> 2;          // A cp rows 0..63 (+64)
    const int cseg = (tid & 3) * 8;
    const int brow = tid >> 5;          // B rows 0..7 (+8*i)
    const int bcol = (lane) * 4;        // B col floats 0..124

    const uint32_t sa0 = (uint32_t)__cvta_generic_to_shared(&As[0][0]);
    const uint32_t sb0 = (uint32_t)__cvta_generic_to_shared(&Bs[0][0]);
    const uint32_t stgA = (uint32_t)(128 * HST * 2);

    const uint32_t offA = (uint32_t)(((wm * 64 + (lane & 15)) * HST + 8 * (lane >> 4)) * 2);
    const uint32_t offB = (uint32_t)((((lane & 7) + 8 * ((lane >> 3) & 1)) * SBN
                                      + wn * 32 + 8 * (lane >> 4)) * 2);

    float acc[4][4][4];
    #pragma unroll
    for (int i = 0; i < 4; i++)
        #pragma unroll
        for (int j = 0; j < 4; j++)
            #pragma unroll
            for (int t = 0; t < 4; t++) acc[i][j][t] = 0.f;

    const int NCH = Kd >> 5;
    const uint32_t cpa = (uint32_t)(crow * HST + cseg) * 2;

    float4 pb[4];

    // prologue: chunk 0
    #pragma unroll
    for (int i = 0; i < 2; i++) {
        int row = crow + 64 * i;
        cp16(sa0 + cpa + (uint32_t)(i * 64 * HST * 2), A + (long)row * lda + cseg);
    }
    #pragma unroll
    for (int i = 0; i < 4; i++)
        pb[i] = *(const float4*)(Bf + (long)(brow + 8 * i) * ldb + bcol);
    cp_commit();
    #pragma unroll
    for (int i = 0; i < 4; i++) {
        uint2 u;
        u.x = h2u(__floats2half2_rn(pb[i].x, pb[i].y));
        u.y = h2u(__floats2half2_rn(pb[i].z, pb[i].w));
        *(uint2*)&Bs[0][(brow + 8 * i) * SBN + bcol] = u;
    }

    for (int kc = 0; kc < NCH; kc++) {
        if (kc + 1 < NCH) {
            const float* Bn = Bf + (long)(kc + 1) * 32 * ldb;
            #pragma unroll
            for (int i = 0; i < 4; i++)
                pb[i] = *(const float4*)(Bn + (long)(brow + 8 * i) * ldb + bcol);
        }

        cp_wait0();
        __syncthreads();

        const int sn = (kc + 1) & 1;
        if (kc + 1 < NCH) {
            const __half* An = A + (long)(kc + 1) * 32;
            #pragma unroll
            for (int i = 0; i < 2; i++)
                cp16(sa0 + (uint32_t)sn * stgA + cpa + (uint32_t)(i * 64 * HST * 2),
                     An + (long)(crow + 64 * i) * lda + cseg);
            cp_commit();
        }

        const uint32_t soA = (uint32_t)(kc & 1) * stgA;
        const uint32_t soB = (uint32_t)(kc & 1) * (uint32_t)(32 * SBN * 2);
        #pragma unroll
        for (int g = 0; g < 2; g++) {
            uint32_t afr[4][4], bfr[2][4];
            #pragma unroll
            for (int mt = 0; mt < 4; mt++)
                ldsm4(afr[mt], sa0 + soA + offA + (uint32_t)(mt * 16 * HST * 2 + g * 32));
            #pragma unroll
            for (int np = 0; np < 2; np++)
                ldsm4t(bfr[np], sb0 + soB + offB + (uint32_t)(np * 32 + g * 16 * SBN * 2));
            #pragma unroll
            for (int mt = 0; mt < 4; mt++)
                #pragma unroll
                for (int np = 0; np < 2; np++) {
                    mma_f16(acc[mt][2 * np],     afr[mt][0], afr[mt][1], afr[mt][2], afr[mt][3],
                            bfr[np][0], bfr[np][1]);
                    mma_f16(acc[mt][2 * np + 1], afr[mt][0], afr[mt][1], afr[mt][2], afr[mt][3],
                            bfr[np][2], bfr[np][3]);
                }
        }

        if (kc + 1 < NCH) {
            __half* bdst = &Bs[sn][0];
            #pragma unroll
            for (int i = 0; i < 4; i++) {
                uint2 u;
                u.x = h2u(__floats2half2_rn(pb[i].x, pb[i].y));
                u.y = h2u(__floats2half2_rn(pb[i].z, pb[i].w));
                *(uint2*)&bdst[(brow + 8 * i) * SBN + bcol] = u;
            }
        }
    }

    #pragma unroll
    for (int mt = 0; mt < 4; mt++) {
        int r0 = wm * 64 + mt * 16 + grp;
        #pragma unroll
        for (int nt = 0; nt < 4; nt++) {
            int c0 = wn * 32 + nt * 8 + 2 * tig;
            *(float2*)(C + (long)r0 * ldc + c0)       = make_float2(acc[mt][nt][0], acc[mt][nt][1]);
            *(float2*)(C + (long)(r0 + 8) * ldc + c0) = make_float2(acc[mt][nt][2], acc[mt][nt][3]);
        }
    }
}

// ---------------- conversion kernels ----------------
__global__ void __launch_bounds__(256) f32_to_f16_vec(
    const float* __restrict__ src, __half* __restrict__ dst)
{
    long i = (long)blockIdx.x * 256 + threadIdx.x;
    float4 v = ((const float4*)src)[i];
    ((__half2*)dst)[2 * i]     = __floats2half2_rn(v.x, v.y);
    ((__half2*)dst)[2 * i + 1] = __floats2half2_rn(v.z, v.w);
}

// dst[C][R] (f32) = src[R][C]^T (f32)  -- used for W^T only
__global__ void __launch_bounds__(256) transpose_f32(
    const float* __restrict__ src, float* __restrict__ dst, int R, int C)
{
    __shared__ float t[32][33];
    int c0 = blockIdx.x * 32, r0 = blockIdx.y * 32;
    int x = threadIdx.x, y = threadIdx.y;
    #pragma unroll
    for (int i = 0; i < 32; i += 8)
        t[y + i][x] = src[(long)(r0 + y + i) * C + c0 + x];
    __syncthreads();
    #pragma unroll
    for (int i = 0; i < 32; i += 8)
        dst[(long)(c0 + y + i) * R + r0 + x] = t[x][y + i];
}

// ---------------- split-K reduction for qW (writes half) ----------------
__global__ void __launch_bounds__(256) reduce_qw(
    const float* __restrict__ part, __half* __restrict__ qW_h)
{
    int i = (blockIdx.x * 256 + threadIdx.x) * 4;
    float4 s = make_float4(0.f, 0.f, 0.f, 0.f);
    #pragma unroll
    for (int z = 0; z < 8; z++) {
        float4 v = *(const float4*)(part + (long)z * (KQ * DIM) + i);
        s.x += v.x; s.y += v.y; s.z += v.z; s.w += v.w;
    }
    const float a = 1.0f / 32.0f;
    ((__half2*)qW_h)[i / 2]     = __floats2half2_rn(s.x * a, s.y * a);
    ((__half2*)qW_h)[i / 2 + 1] = __floats2half2_rn(s.z * a, s.w * a);
}

// ---------------- mask dtype detection ----------------
__global__ void detect_mask_kind(const unsigned char* __restrict__ m)
{
    if (threadIdx.x != 0 || blockIdx.x != 0) return;
    int cnt[4] = {0, 0, 0, 0};
    for (int i = 0; i < 4096; i++)
        if (m[i] != 0) cnt[i & 3]++;
    int kind;
    if (cnt[1] > 0)                    kind = 1;  // uint8 bool
    else if (cnt[2] > 0 || cnt[3] > 0) kind = 2;  // float32
    else                               kind = 0;  // int32 bool
    g_mask_kind = kind;
}

// ---------------- fused mask + softmax (fp32 att + half att) ----------------
__global__ void __launch_bounds__(256) mask_softmax(
    float* __restrict__ att, __half* __restrict__ att_h, const void* __restrict__ mask_raw)
{
    long row = blockIdx.x;
    float* p = att + row * (long)NK;
    __half* ph = att_h + row * (long)NK;
    int tid = threadIdx.x;
    int kind = g_mask_kind;

    const unsigned char* m8  = (const unsigned char*)mask_raw + row * (long)NK;
    const int*           m32 = (const int*)mask_raw           + row * (long)NK;
    const float*         mf  = (const float*)mask_raw         + row * (long)NK;

    float v[8];
    float lmax = -INFINITY;
    #pragma unroll
    for (int i = 0; i < 8; i++) {
        int idx = tid + i * 256;
        bool keep;
        if (kind == 0)      keep = (m32[idx] != 0);
        else if (kind == 1) keep = (m8[idx] != 0);
        else                keep = (mf[idx] != 0.0f);
        float s = keep ? p[idx] : -INFINITY;
        v[i] = s;
        lmax = fmaxf(lmax, s);
    }

    __shared__ float red[8];
    #pragma unroll
    for (int o = 16; o > 0; o >>= 1)
        lmax = fmaxf(lmax, __shfl_xor_sync(0xffffffffu, lmax, o));
    if ((tid & 31) == 0) red[tid >> 5] = lmax;
    __syncthreads();
    float rmax = fmaxf(fmaxf(fmaxf(red[0], red[1]), fmaxf(red[2], red[3])),
                       fmaxf(fmaxf(red[4], red[5]), fmaxf(red[6], red[7])));
    __syncthreads();

    float lsum = 0.f;
    #pragma unroll
    for (int i = 0; i < 8; i++) {
        float e = (v[i] == -INFINITY) ? 0.f : __expf(v[i] - rmax);
        v[i] = e;
        lsum += e;
    }
    #pragma unroll
    for (int o = 16; o > 0; o >>= 1)
        lsum += __shfl_xor_sync(0xffffffffu, lsum, o);
    if ((tid & 31) == 0) red[tid >> 5] = lsum;
    __syncthreads();
    float rsum = red[0] + red[1] + red[2] + red[3] + red[4] + red[5] + red[6] + red[7];
    float inv = (rsum > 0.f) ? (1.f / rsum) : 0.f;

    #pragma unroll
    for (int i = 0; i < 8; i++) {
        float r = v[i] * inv;
        int idx = tid + i * 256;
        p[idx] = r;
        ph[idx] = __float2half(r);
    }
}

// ---------------- launcher ----------------
extern "C" void kernel_launch(void* const* d_in, const int* in_sizes, int n_in,
                              void* d_out, int out_size)
{
    const float* query = (const float*)d_in[0];   // [KQ, DIM]
    const float* key   = (const float*)d_in[1];   // [BATCH, NK, DIM]
    const float* W     = (const float*)d_in[2];   // [DIM, DIM]
    const void*  mask  = d_in[3];                 // [BATCH, KQ, NK] bool

    float* out_ptr = (float*)d_out;
    const long outBKD = (long)BATCH * KQ * DIM;

    float *qW_part, *att_scratch, *WT_f;
    __half *qW_h, *query_h, *att_h;
    cudaGetSymbolAddress((void**)&qW_part, g_qW_part);
    cudaGetSymbolAddress((void**)&qW_h, g_qW_h);
    cudaGetSymbolAddress((void**)&query_h, g_query_h);
    cudaGetSymbolAddress((void**)&WT_f, g_WT_f);
    cudaGetSymbolAddress((void**)&att_h, g_att_h);
    cudaGetSymbolAddress((void**)&att_scratch, g_att_scratch);

    float* att_ptr = ((long)out_size > outBKD) ? (out_ptr + outBKD) : att_scratch;

    // 0) mask dtype detection
    detect_mask_kind<<<1, 1>>>((const unsigned char*)mask);

    // 1) conversions: query -> half, W -> W^T (f32). key stays f32 (GEMMs convert in-flight)
    f32_to_f16_vec<<<(KQ * DIM / 4) / 256, 256>>>(query, query_h);
    transpose_f32<<<dim3(DIM / 32, DIM / 32), dim3(32, 8)>>>(W, WT_f, DIM, DIM);

    // 2) qW partials via split-K=8 (NT: A=query_h, B=WT_f f32), reduce (/32) -> half
    gemm_nt_h<<<dim3(DIM / 128, KQ / 128, 8), 256>>>(
        query_h, WT_f, qW_part, 128, DIM, DIM, DIM,
        128L, 128L, (long)KQ * DIM);
    reduce_qw<<<KQ * DIM / (256 * 4), 256>>>(qW_part, qW_h);

    // 3) scores[b] = qW_h @ key[b]^T   (NT, key read as f32 directly)
    gemm_nt_h<<<dim3(NK / 128, KQ / 128, BATCH), 256>>>(
        qW_h, key, att_ptr, DIM, DIM, DIM, NK,
        0L, (long)NK * DIM, (long)KQ * NK);

    // 4) mask + softmax in place (fp32 out) + half copy
    mask_softmax<<<BATCH * KQ, 256>>>(att_ptr, att_h, mask);

    // 5) out[b] = att_h[b] @ key[b]    (NN, key f32 native layout)
    gemm_nn_h<<<dim3(DIM / 128, KQ / 128, BATCH), 256>>>(
        att_h, key, out_ptr, NK, NK, DIM, DIM,
        (long)KQ * NK, (long)NK * DIM, (long)KQ * DIM);
}